// round 1
// baseline (speedup 1.0000x reference)
#include <cuda_runtime.h>
#include <math.h>

#define DD   128        // embedding dim
#define HH   256        // hyper hidden
#define EMAX 500000
#define SLOTMAX 250000  // worst case: every multi-group has exactly 2 edges

// ---------------- device scratch (static; no allocation) ----------------
__device__ float    g_mid[4];
__device__ float    g_Wq[DD*DD];
__device__ float    g_Wk[DD*DD];
__device__ float    g_M [DD*DD];
__device__ int      g_counts[EMAX];
__device__ int      g_slot  [EMAX];
__device__ float    g_gsum  [(size_t)SLOTMAX * DD];   // group sums, then u = M^T s (in place)
__device__ unsigned g_gmax  [SLOTMAX];
__device__ float    g_gdenom[SLOTMAX];
__device__ float    g_score [EMAX];
__device__ int      g_medges[EMAX];
__device__ int      g_nslots;
__device__ int      g_nmedges;

// monotonic float<->uint encoding for atomicMax over signed floats
__device__ __forceinline__ unsigned fenc(float f) {
    unsigned u = __float_as_uint(f);
    return (u & 0x80000000u) ? ~u : (u | 0x80000000u);
}
__device__ __forceinline__ float fdec(unsigned e) {
    return __uint_as_float((e & 0x80000000u) ? (e ^ 0x80000000u) : ~e);
}

// ---------------- kernels ----------------

__global__ void k_zero(int E) {
    int e = blockIdx.x * blockDim.x + threadIdx.x;
    if (e < E) g_counts[e] = 0;
    if (e == 0) { g_nslots = 0; g_nmedges = 0; }
}

// hypernetwork: pref(2) -> h1(256) -> h2(256) -> mid(4)
__global__ void k_hyper(const float* __restrict__ pref,
                        const float* __restrict__ fc1_w, const float* __restrict__ fc1_b,
                        const float* __restrict__ fc2_w, const float* __restrict__ fc2_b,
                        const float* __restrict__ fc3_w, const float* __restrict__ fc3_b) {
    __shared__ float h1[HH];
    __shared__ float h2[HH];
    int t = threadIdx.x;
    float p0 = pref[0], p1 = pref[1];
    h1[t] = p0 * fc1_w[2*t] + p1 * fc1_w[2*t + 1] + fc1_b[t];
    __syncthreads();
    float acc = fc2_b[t];
    #pragma unroll 8
    for (int k = 0; k < HH; k++) acc += h1[k] * fc2_w[t*HH + k];
    h2[t] = acc;
    __syncthreads();
    if (t < 4) {
        float a = fc3_b[t];
        for (int k = 0; k < HH; k++) a += h2[k] * fc3_w[t*HH + k];
        g_mid[t] = a;
    }
}

// Wq[i] = mid0*wq_w[i,0] + mid1*wq_w[i,1]; Wk similarly with mid2/mid3
__global__ void k_w(const float* __restrict__ wq_w, const float* __restrict__ wk_w) {
    int i = blockIdx.x * blockDim.x + threadIdx.x;
    if (i >= DD*DD) return;
    float m0 = g_mid[0], m1 = g_mid[1], m2 = g_mid[2], m3 = g_mid[3];
    g_Wq[i] = m0 * wq_w[2*i] + m1 * wq_w[2*i + 1];
    g_Wk[i] = m2 * wk_w[2*i] + m3 * wk_w[2*i + 1];
}

// M[r,c] = sum_o Wq[o,r] * Wk[o,c]   (one block per row r)
__global__ void k_m() {
    __shared__ float col[DD];
    int c = threadIdx.x, r = blockIdx.x;
    col[c] = g_Wq[c*DD + r];
    __syncthreads();
    float acc = 0.f;
    #pragma unroll 8
    for (int o = 0; o < DD; o++) acc += col[o] * g_Wk[o*DD + c];
    g_M[r*DD + c] = acc;
}

// count group sizes; the edge observing old==1 claims a compact slot & inits it
__global__ void k_count(const int* __restrict__ seg, int E) {
    int e = blockIdx.x * blockDim.x + threadIdx.x;
    if (e >= E) return;
    int g = seg[e];
    int old = atomicAdd(&g_counts[g], 1);
    if (old == 1) {
        int slot = atomicAdd(&g_nslots, 1);
        g_slot[g]   = slot;
        g_gmax[slot]   = 0u;     // < fenc of any finite float
        g_gdenom[slot] = 0.f;
        float4 z = make_float4(0.f, 0.f, 0.f, 0.f);
        float4* row = (float4*)&g_gsum[(size_t)slot * DD];
        #pragma unroll
        for (int i = 0; i < DD/4; i++) row[i] = z;
    }
}

// singleton groups -> prob is exactly 1.0; multi edges compacted into g_medges
__global__ void k_mark(const int* __restrict__ seg, float* __restrict__ out, int E) {
    int e = blockIdx.x * blockDim.x + threadIdx.x;
    if (e >= E) return;
    int g = seg[e];
    if (g_counts[g] == 1) {
        out[e] = 1.0f;
    } else {
        int i = atomicAdd(&g_nmedges, 1);
        g_medges[i] = e;
    }
}

// accumulate edge_emb into group sums (multi edges only); one warp per edge
__global__ void k_accum(const int* __restrict__ seg, const float* __restrict__ emb) {
    int lane = threadIdx.x & 31;
    int w  = (blockIdx.x * blockDim.x + threadIdx.x) >> 5;
    int nw = (gridDim.x * blockDim.x) >> 5;
    int n = g_nmedges;
    for (int i = w; i < n; i += nw) {
        int e = g_medges[i];
        size_t base = (size_t)g_slot[seg[e]] * DD;
        const float* x = emb + (size_t)e * DD;
        #pragma unroll
        for (int j = 0; j < 4; j++)
            atomicAdd(&g_gsum[base + lane + 32*j], x[lane + 32*j]);
    }
}

// u = M^T * sum (in place); 4 slots per block so M is read once per 4 matvecs
__global__ void k_u() {
    __shared__ float sm[4][DD];
    int t = threadIdx.x;
    int ns = g_nslots;
    for (int s0 = blockIdx.x * 4; s0 < ns; s0 += gridDim.x * 4) {
        #pragma unroll
        for (int k = 0; k < 4; k++)
            sm[k][t] = (s0 + k < ns) ? g_gsum[(size_t)(s0 + k) * DD + t] : 0.f;
        __syncthreads();
        float a0 = 0.f, a1 = 0.f, a2 = 0.f, a3 = 0.f;
        #pragma unroll 4
        for (int d = 0; d < DD; d++) {
            float mv = g_M[d*DD + t];
            a0 += sm[0][d] * mv;
            a1 += sm[1][d] * mv;
            a2 += sm[2][d] * mv;
            a3 += sm[3][d] * mv;
        }
        __syncthreads();
        g_gsum[(size_t)s0 * DD + t] = a0;
        if (s0 + 1 < ns) g_gsum[(size_t)(s0+1) * DD + t] = a1;
        if (s0 + 2 < ns) g_gsum[(size_t)(s0+2) * DD + t] = a2;
        if (s0 + 3 < ns) g_gsum[(size_t)(s0+3) * DD + t] = a3;
        __syncthreads();
    }
}

// score_e = 10*tanh( (u_g . x_e)/(c*8*sqrt(128)) - d_e/sqrt(2) ); track group max
__global__ void k_score(const int* __restrict__ seg, const float* __restrict__ emb,
                        const float* __restrict__ dists, const float* __restrict__ pref) {
    int lane = threadIdx.x & 31;
    int w  = (blockIdx.x * blockDim.x + threadIdx.x) >> 5;
    int nw = (gridDim.x * blockDim.x) >> 5;
    int n = g_nmedges;
    float p0 = pref[0], p1 = pref[1];
    const float inv_scale = 0.011048543456039805f;  // 1/(8*sqrt(128))
    const float inv_sqrt2 = 0.7071067811865476f;
    for (int i = w; i < n; i += nw) {
        int e = g_medges[i];
        int g = seg[e];
        int slot = g_slot[g];
        float c = (float)g_counts[g];
        const float4* u = (const float4*)&g_gsum[(size_t)slot * DD];
        const float4* x = (const float4*)&emb[(size_t)e * DD];
        float4 uv = u[lane];
        float4 xv = x[lane];
        float dot = uv.x*xv.x + uv.y*xv.y + uv.z*xv.z + uv.w*xv.w;
        #pragma unroll
        for (int o = 16; o > 0; o >>= 1) dot += __shfl_xor_sync(0xffffffffu, dot, o);
        if (lane == 0) {
            float de = p0 * dists[2*e] + p1 * dists[2*e + 1];
            float s = dot * inv_scale / c - de * inv_sqrt2;
            s = 10.0f * tanhf(s);
            g_score[e] = s;
            atomicMax(&g_gmax[slot], fenc(s));
        }
    }
}

__global__ void k_ex(const int* __restrict__ seg) {
    int i0 = blockIdx.x * blockDim.x + threadIdx.x;
    int stride = gridDim.x * blockDim.x;
    int n = g_nmedges;
    for (int i = i0; i < n; i += stride) {
        int e = g_medges[i];
        int slot = g_slot[seg[e]];
        float ex = expf(g_score[e] - fdec(g_gmax[slot]));
        g_score[e] = ex;
        atomicAdd(&g_gdenom[slot], ex);
    }
}

__global__ void k_out(const int* __restrict__ seg, float* __restrict__ out) {
    int i0 = blockIdx.x * blockDim.x + threadIdx.x;
    int stride = gridDim.x * blockDim.x;
    int n = g_nmedges;
    for (int i = i0; i < n; i += stride) {
        int e = g_medges[i];
        int slot = g_slot[seg[e]];
        out[e] = g_score[e] / g_gdenom[slot];
    }
}

// ---------------- launch ----------------
extern "C" void kernel_launch(void* const* d_in, const int* in_sizes, int n_in,
                              void* d_out, int out_size) {
    const float* pref     = (const float*)d_in[0];
    const float* dists    = (const float*)d_in[1];
    const float* edge_emb = (const float*)d_in[2];
    const int*   seg      = (const int*)  d_in[3];
    const float* fc1_w    = (const float*)d_in[4];
    const float* fc1_b    = (const float*)d_in[5];
    const float* fc2_w    = (const float*)d_in[6];
    const float* fc2_b    = (const float*)d_in[7];
    const float* fc3_w    = (const float*)d_in[8];
    const float* fc3_b    = (const float*)d_in[9];
    const float* wq_w     = (const float*)d_in[10];
    const float* wk_w     = (const float*)d_in[11];
    float* out = (float*)d_out;

    int E = in_sizes[3];
    int EB = (E + 255) / 256;

    k_zero <<<EB, 256>>>(E);
    k_hyper<<<1, 256>>>(pref, fc1_w, fc1_b, fc2_w, fc2_b, fc3_w, fc3_b);
    k_w    <<<(DD*DD + 255)/256, 256>>>(wq_w, wk_w);
    k_m    <<<DD, DD>>>();
    k_count<<<EB, 256>>>(seg, E);
    k_mark <<<EB, 256>>>(seg, out, E);
    k_accum<<<512, 256>>>(seg, edge_emb);
    k_u    <<<4096, 128>>>();
    k_score<<<1024, 256>>>(seg, edge_emb, dists, pref);
    k_ex   <<<256, 256>>>(seg);
    k_out  <<<256, 256>>>(seg, out);
}